// round 12
// baseline (speedup 1.0000x reference)
#include <cuda_runtime.h>
#include <cuda_bf16.h>
#include <cstddef>

// B=32, T=32768, K=N=8, D=256
// Balanced warp-tile decomposition: 4096 tiles x 256 rows, 592 blocks
// (148 SMs x 4 CTAs, idle warps evenly spread). Round-3 mma inner loop.
//   nlp = softplus(-x); p2 = sigmoid(x)^2
//   u = 4*nlp - x ; w = p2*x
//   A[k][n] = sum u*y ; W[k][n] = sum w*y   (mma.m16n8k16 bf16, u/w rows stacked)
//   S1[k] = sum (nlp+x) ; S2[k] = sum p2*(nlp+0.9x)
//   cost = (S1+A)/T ; assign_k = 0.75*(S2[k] - 0.8*W[k][col_k])

#define FULLMASK 0xffffffffu
#define NTILE 4096         // 32 batches x 128 tiles of 256 rows
#define GRID1 592
#define SLOT 145           // 64 A + 64 W + 8 S1 + 8 S2 + 1 overlap

__device__ float gPart[NTILE * SLOT];
__device__ float gTotal;
__device__ unsigned gCount;

__device__ __forceinline__ unsigned pk(float hi, float lo) {
    unsigned r;
    asm("cvt.rn.bf16x2.f32 %0, %1, %2;" : "=r"(r) : "f"(hi), "f"(lo));
    return r;
}

__device__ __forceinline__ void procE(float x, float& u, float& w,
                                      float& s1, float& s2) {
    float e = __expf(-x);
    float tt = 1.f + e;
    float nlp = __logf(tt);
    float r;
    asm("rcp.approx.ftz.f32 %0, %1;" : "=f"(r) : "f"(tt));
    float p2 = r * r;                     // sigmoid(x)^2
    u = fmaf(4.f, nlp, -x);
    w = p2 * x;
    s1 += nlp + x;
    s2 = fmaf(p2, fmaf(0.9f, x, nlp), s2);
}

__global__ void __launch_bounds__(256, 4)
main_kernel(const float* __restrict__ logits, const float* __restrict__ labels,
            const float* __restrict__ olg, const float* __restrict__ otg) {
    const int tid = threadIdx.x;
    const int bid = blockIdx.x;
    if (bid == 0 && tid == 0) { gTotal = 0.f; gCount = 0u; }

    // block's contiguous tile range: [bid*256/37, (bid+1)*256/37) — 6 or 7 tiles
    const int start = (bid * 256) / 37;
    const int end   = ((bid + 1) * 256) / 37;
    const int wrp = tid >> 5, l = tid & 31;
    const int tau = start + wrp;
    if (tau >= end) return;               // no barriers in this kernel: safe

    const int b  = tau >> 7;              // 128 tiles per batch
    const int t0 = (tau & 127) << 8;      // 256-row tile
    const int gid = l >> 2, tg = l & 3;
    const int o0 = 16 * tg, o1 = o0 + 8, o2 = o0 + 64, o3 = o0 + 72;

    // ---- overlap MSE: this tile's 256 rows, 2 float4 per lane ----
    const float4* ob = reinterpret_cast<const float4*>(olg + (size_t)b * 32768 + t0);
    const float4* tb = reinterpret_cast<const float4*>(otg + (size_t)b * 32768 + t0);
    float ov;
    {
        float4 oA = ob[l], tA = tb[l], oB = ob[l + 32], tB = tb[l + 32];
        float d0 = oA.x - tA.x, d1 = oA.y - tA.y, d2 = oA.z - tA.z, d3 = oA.w - tA.w;
        float d4 = oB.x - tB.x, d5 = oB.y - tB.y, d6 = oB.z - tB.z, d7 = oB.w - tB.w;
        ov = fmaf(d0, d0, fmaf(d1, d1, fmaf(d2, d2, fmaf(d3, d3,
             fmaf(d4, d4, fmaf(d5, d5, fmaf(d6, d6, d7 * d7)))))));
    }

    // ---- mma streaming: 16 steps of 16 rows (round-3 inner loop) ----
    const float* xp = logits + ((size_t)b * 32768 + t0) * 8 + gid;
    const float* yp = labels + ((size_t)b * 32768 + t0) * 8 + gid;

    float c0 = 0.f, c1 = 0.f, c2 = 0.f, c3 = 0.f, s1 = 0.f, s2 = 0.f;

#pragma unroll 4
    for (int i = 0; i < 16; i++) {
        const int base = i * 128;
        float x0 = xp[base + o0], x1 = xp[base + o1];
        float x2 = xp[base + o2], x3 = xp[base + o3];
        float y0 = yp[base + o0], y1 = yp[base + o1];
        float y2 = yp[base + o2], y3 = yp[base + o3];
        float u0, u1, u2, u3, w0, w1, w2, w3;
        procE(x0, u0, w0, s1, s2);
        procE(x1, u1, w1, s1, s2);
        procE(x2, u2, w2, s1, s2);
        procE(x3, u3, w3, s1, s2);
        unsigned a0 = pk(u1, u0), a1 = pk(w1, w0);
        unsigned a2 = pk(u3, u2), a3 = pk(w3, w2);
        unsigned b0 = pk(y1, y0), b1 = pk(y3, y2);
        asm("mma.sync.aligned.m16n8k16.row.col.f32.bf16.bf16.f32 "
            "{%0,%1,%2,%3}, {%4,%5,%6,%7}, {%8,%9}, {%0,%1,%2,%3};"
            : "+f"(c0), "+f"(c1), "+f"(c2), "+f"(c3)
            : "r"(a0), "r"(a1), "r"(a2), "r"(a3), "r"(b0), "r"(b1));
    }

    // s1/s2: reduce across the 4 lanes of each gid group
    s1 += __shfl_xor_sync(FULLMASK, s1, 1);
    s1 += __shfl_xor_sync(FULLMASK, s1, 2);
    s2 += __shfl_xor_sync(FULLMASK, s2, 1);
    s2 += __shfl_xor_sync(FULLMASK, s2, 2);
#pragma unroll
    for (int off = 16; off >= 1; off >>= 1) ov += __shfl_down_sync(FULLMASK, ov, off);

    // direct per-warp tile partial stores (no shared accumulation)
    float* gp = gPart + (size_t)tau * SLOT;
    gp[gid * 8 + 2 * tg]          = c0;
    gp[gid * 8 + 2 * tg + 1]      = c1;
    gp[64 + gid * 8 + 2 * tg]     = c2;
    gp[64 + gid * 8 + 2 * tg + 1] = c3;
    if (tg == 0) {
        gp[128 + gid] = s1;
        gp[136 + gid] = s2;
    }
    if (l == 0) gp[144] = ov;
}

// Per-batch: 128-tile reduce + gram + subset-DP assignment + existence; last
// block folds everything into the scalar output. (Round-3/11 validated.)
__global__ void __launch_bounds__(256)
batch_kernel(const float* __restrict__ att, const float* __restrict__ exist,
             float* __restrict__ out, int out_size) {
    __shared__ float red[SLOT];
    __shared__ float rb[37];     // 36 gram upper-tri + [36] existence sum
    __shared__ float csh[64];
    __shared__ float dp[256];
    __shared__ int   ch[256];
    __shared__ int   sLast;
    __shared__ float sTot;
    const int b = blockIdx.x, tid = threadIdx.x;

    if (tid < SLOT) {
        const float* gp = gPart + (size_t)b * 128 * SLOT + tid;
        float s = 0.f;
#pragma unroll 16
        for (int c = 0; c < 128; c++) s += gp[c * SLOT];
        red[tid] = s;
    }
    if (tid < 37) rb[tid] = 0.f;
    if (tid == 0) { dp[0] = 0.f; sLast = 0; }
    __syncthreads();

    if (tid < 64) {
        int k = tid >> 3;
        float cc = (red[128 + k] + red[tid]) * (1.f / 32768.f);
        if (!(fabsf(cc) <= 1e30f)) cc = 100.f;
        csh[tid] = cc;
    }
    if (tid < 8) {
        float e  = exist[b * 8 + tid];
        float ll = __logf(1.f + __expf(-fabsf(e)));
        float spn = ll + fmaxf(-e, 0.f);
        float spp = ll + fmaxf(e, 0.f);
        atomicAdd(&rb[36], 4.5f * spn + 0.1f * spp);
    }

    // attractor gram: thread = dim d (256 dims, fully parallel)
    const float* ab = att + (size_t)b * 8 * 256;
    float a[8];
#pragma unroll
    for (int k = 0; k < 8; k++) a[k] = ab[k * 256 + tid];
    float cp[36];
    {
        int idx = 0;
#pragma unroll
        for (int k = 0; k < 8; k++)
#pragma unroll
            for (int j = k; j < 8; j++) cp[idx++] = a[k] * a[j];
    }
#pragma unroll
    for (int off = 16; off >= 1; off >>= 1)
#pragma unroll
        for (int i = 0; i < 36; i++) cp[i] += __shfl_down_sync(FULLMASK, cp[i], off);
    if ((tid & 31) == 0)
#pragma unroll
        for (int i = 0; i < 36; i++) atomicAdd(&rb[i], cp[i]);

    // subset-DP exact assignment (level-synchronous over popcount)
    for (int r = 1; r <= 8; r++) {
        __syncthreads();
        int m = tid;
        if (m >= 1 && m < 256 && __popc(m) == r) {
            float best = 1e30f; int bn = 0;
#pragma unroll
            for (int n = 0; n < 8; n++) {
                if (m & (1 << n)) {
                    float v = dp[m ^ (1 << n)] + csh[(r - 1) * 8 + n];
                    if (v < best) { best = v; bn = n; }
                }
            }
            dp[m] = best; ch[m] = bn;
        }
    }
    __syncthreads();

    if (tid == 0) {
        float nrm[8]; int di = 0;
        for (int k = 0; k < 8; k++) { nrm[k] = fmaxf(sqrtf(rb[di]), 1e-12f); di += 8 - k; }
        float ortho = 0.f, contr = 0.f; int idx = 0;
        for (int k = 0; k < 8; k++)
            for (int j = k; j < 8; j++) {
                float s = rb[idx] / (nrm[k] * nrm[j]);
                if (j == k) { float d = s - 1.f; ortho += d * d; }
                else { ortho += 2.f * s * s; contr += 2.f * fmaxf(s + 0.5f, 0.f); }
                idx++;
            }

        int mask = 255, col[8];
        for (int r = 7; r >= 0; --r) { int n = ch[mask]; col[r] = n; mask ^= (1 << n); }
        float asn = 0.f;
        for (int k = 0; k < 8; k++)
            asn += 0.75f * (red[136 + k] - 0.8f * red[64 + k * 8 + col[k]]);

        float contrib = asn * (1.f / 8388608.f)          // assign mean (B*T*K)
                      + rb[36] * (1.f / 256.f)           // exist mean
                      + 0.1f * ortho * (1.f / 2048.f)    // ortho mean
                      + 0.1f * contr * (1.f / 1792.f)    // contrast
                      + 0.5f * red[144] * (1.f / 1048576.f); // overlap mean
        atomicAdd(&gTotal, contrib);
        __threadfence();
        unsigned old = atomicAdd(&gCount, 1u);
        if (old == 31u) { sLast = 1; sTot = atomicAdd(&gTotal, 0.f); }
    }
    __syncthreads();
    if (sLast) {
        float t = sTot;
        for (int i = tid; i < out_size; i += blockDim.x) out[i] = t;
    }
}

extern "C" void kernel_launch(void* const* d_in, const int* in_sizes, int n_in,
                              void* d_out, int out_size) {
    const float* logits    = (const float*)d_in[0];
    const float* existence = (const float*)d_in[1];
    const float* attract   = (const float*)d_in[2];
    const float* labels    = (const float*)d_in[3];
    const float* olg       = (const float*)d_in[4];
    const float* otg       = (const float*)d_in[5];
    float* out = (float*)d_out;

    main_kernel<<<GRID1, 256>>>(logits, labels, olg, otg);
    batch_kernel<<<32, 256>>>(attract, existence, out, out_size);
}

// round 13
// speedup vs baseline: 1.0112x; 1.0112x over previous
#include <cuda_runtime.h>
#include <cuda_bf16.h>
#include <cstddef>

// B=32, T=32768, K=N=8, D=256
// Round-3 champion + L2 prefetch (distance-4) in the streaming loop.
//   nlp = softplus(-x); p2 = sigmoid(x)^2
//   u = 4*nlp - x ; w = p2*x
//   A[k][n] = sum u*y ; W[k][n] = sum w*y   (mma.m16n8k16 bf16, u/w rows stacked)
//   S1[k] = sum (nlp+x) ; S2[k] = sum p2*(nlp+0.9x)
//   cost = (S1+A)/T ; assign_k = 0.75*(S2[k] - 0.8*W[k][col_k])

#define FULLMASK 0xffffffffu
#define CHUNKS 16
#define TPB_T 2048
#define SLOT 145   // 64 A + 64 W + 8 S1 + 8 S2 + 1 overlap

__device__ float gPart[32 * CHUNKS * SLOT];
__device__ float gTotal;
__device__ unsigned gCount;

__device__ __forceinline__ unsigned pk(float hi, float lo) {
    unsigned r;
    asm("cvt.rn.bf16x2.f32 %0, %1, %2;" : "=r"(r) : "f"(hi), "f"(lo));
    return r;
}

__device__ __forceinline__ void procE(float x, float& u, float& w,
                                      float& s1, float& s2) {
    float e = __expf(-x);
    float tt = 1.f + e;
    float nlp = __logf(tt);
    float r;
    asm("rcp.approx.ftz.f32 %0, %1;" : "=f"(r) : "f"(tt));
    float p2 = r * r;                     // sigmoid(x)^2
    u = fmaf(4.f, nlp, -x);
    w = p2 * x;
    s1 += nlp + x;
    s2 = fmaf(p2, fmaf(0.9f, x, nlp), s2);
}

__global__ void __launch_bounds__(256, 4)
main_kernel(const float* __restrict__ logits, const float* __restrict__ labels,
            const float* __restrict__ olg, const float* __restrict__ otg) {
    __shared__ float sAcc[SLOT];
    const int tid = threadIdx.x;
    if (tid < SLOT) sAcc[tid] = 0.f;
    if (blockIdx.x == 0 && blockIdx.y == 0 && tid == 0) { gTotal = 0.f; gCount = 0u; }
    __syncthreads();

    const int b = blockIdx.y, c = blockIdx.x;
    const int t0 = c * TPB_T;
    const float* lg = logits + (size_t)b * 32768 * 8;
    const float* yb = labels + (size_t)b * 32768 * 8;

    // ---- overlap MSE (coalesced float4) ----
    const float* ob = olg + (size_t)b * 32768 + t0;
    const float* tb = otg + (size_t)b * 32768 + t0;
    float ov = 0.f;
    for (int i = tid; i < TPB_T / 4; i += 256) {
        float4 o4 = reinterpret_cast<const float4*>(ob)[i];
        float4 t4 = reinterpret_cast<const float4*>(tb)[i];
        float d0 = o4.x - t4.x, d1 = o4.y - t4.y;
        float d2 = o4.z - t4.z, d3 = o4.w - t4.w;
        ov = fmaf(d0, d0, fmaf(d1, d1, fmaf(d2, d2, fmaf(d3, d3, ov))));
    }

    // ---- main mma loop: warp covers 256 t's as 16 steps of 16 ----
    const int wrp = tid >> 5, l = tid & 31;
    const int gid = l >> 2, tg = l & 3;
    const int tw = t0 + wrp * 256;
    const float* xp = lg + (size_t)tw * 8 + gid;
    const float* yp = yb + (size_t)tw * 8 + gid;
    const int o0 = 16 * tg, o1 = o0 + 8, o2 = o0 + 64, o3 = o0 + 72;

    float c0 = 0.f, c1 = 0.f, c2 = 0.f, c3 = 0.f, s1 = 0.f, s2 = 0.f;

#pragma unroll 4
    for (int i = 0; i < 16; i++) {
        const int base = i * 128;

        // L2 prefetch, distance 4: the tile at i+4 spans 4 aligned 128B
        // lines per tensor; lanes 0-3 (gid==0) cover them. Zero regs held.
        const int pfb = ((i + 4) & 15) * 128;
        if (l < 4) {
            asm volatile("prefetch.global.L2 [%0];" :: "l"(xp + pfb + l * 32));
            asm volatile("prefetch.global.L2 [%0];" :: "l"(yp + pfb + l * 32));
        }

        float x0 = xp[base + o0], x1 = xp[base + o1];
        float x2 = xp[base + o2], x3 = xp[base + o3];
        float y0 = yp[base + o0], y1 = yp[base + o1];
        float y2 = yp[base + o2], y3 = yp[base + o3];
        float u0, u1, u2, u3, w0, w1, w2, w3;
        procE(x0, u0, w0, s1, s2);
        procE(x1, u1, w1, s1, s2);
        procE(x2, u2, w2, s1, s2);
        procE(x3, u3, w3, s1, s2);
        unsigned a0 = pk(u1, u0), a1 = pk(w1, w0);
        unsigned a2 = pk(u3, u2), a3 = pk(w3, w2);
        unsigned b0 = pk(y1, y0), b1 = pk(y3, y2);
        asm("mma.sync.aligned.m16n8k16.row.col.f32.bf16.bf16.f32 "
            "{%0,%1,%2,%3}, {%4,%5,%6,%7}, {%8,%9}, {%0,%1,%2,%3};"
            : "+f"(c0), "+f"(c1), "+f"(c2), "+f"(c3)
            : "r"(a0), "r"(a1), "r"(a2), "r"(a3), "r"(b0), "r"(b1));
    }

    // s1/s2: reduce across the 4 lanes of each gid group
    s1 += __shfl_xor_sync(FULLMASK, s1, 1);
    s1 += __shfl_xor_sync(FULLMASK, s1, 2);
    s2 += __shfl_xor_sync(FULLMASK, s2, 1);
    s2 += __shfl_xor_sync(FULLMASK, s2, 2);
#pragma unroll
    for (int off = 16; off >= 1; off >>= 1) ov += __shfl_down_sync(FULLMASK, ov, off);

    // C frag: c0=(gid,2tg) c1=(gid,2tg+1) rows 0-7 = A ; c2,c3 rows 8-15 = W
    atomicAdd(&sAcc[gid * 8 + 2 * tg],          c0);
    atomicAdd(&sAcc[gid * 8 + 2 * tg + 1],      c1);
    atomicAdd(&sAcc[64 + gid * 8 + 2 * tg],     c2);
    atomicAdd(&sAcc[64 + gid * 8 + 2 * tg + 1], c3);
    if (tg == 0) {
        atomicAdd(&sAcc[128 + gid], s1);
        atomicAdd(&sAcc[136 + gid], s2);
    }
    if (l == 0) atomicAdd(&sAcc[144], ov);
    __syncthreads();

    if (tid < SLOT) gPart[(b * CHUNKS + c) * SLOT + tid] = sAcc[tid];
}

// Per-batch: chunk reduce + gram + subset-DP assignment + existence; last block
// folds everything into the scalar output. (Round-3 validated.)
__global__ void __launch_bounds__(256)
batch_kernel(const float* __restrict__ att, const float* __restrict__ exist,
             float* __restrict__ out, int out_size) {
    __shared__ float red[SLOT];
    __shared__ float rb[37];     // 36 gram upper-tri + [36] existence sum
    __shared__ float csh[64];
    __shared__ float dp[256];
    __shared__ int   ch[256];
    __shared__ int   sLast;
    __shared__ float sTot;
    const int b = blockIdx.x, tid = threadIdx.x;

    if (tid < SLOT) {
        float s = 0.f;
#pragma unroll
        for (int c = 0; c < CHUNKS; c++) s += gPart[(b * CHUNKS + c) * SLOT + tid];
        red[tid] = s;
    }
    if (tid < 37) rb[tid] = 0.f;
    if (tid == 0) { dp[0] = 0.f; sLast = 0; }
    __syncthreads();

    if (tid < 64) {
        int k = tid >> 3;
        float cc = (red[128 + k] + red[tid]) * (1.f / 32768.f);
        if (!(fabsf(cc) <= 1e30f)) cc = 100.f;
        csh[tid] = cc;
    }
    if (tid < 8) {
        float e  = exist[b * 8 + tid];
        float ll = __logf(1.f + __expf(-fabsf(e)));
        float spn = ll + fmaxf(-e, 0.f);
        float spp = ll + fmaxf(e, 0.f);
        atomicAdd(&rb[36], 4.5f * spn + 0.1f * spp);
    }

    // attractor gram: thread = dim d (256 dims, fully parallel)
    const float* ab = att + (size_t)b * 8 * 256;
    float a[8];
#pragma unroll
    for (int k = 0; k < 8; k++) a[k] = ab[k * 256 + tid];
    float cp[36];
    {
        int idx = 0;
#pragma unroll
        for (int k = 0; k < 8; k++)
#pragma unroll
            for (int j = k; j < 8; j++) cp[idx++] = a[k] * a[j];
    }
#pragma unroll
    for (int off = 16; off >= 1; off >>= 1)
#pragma unroll
        for (int i = 0; i < 36; i++) cp[i] += __shfl_down_sync(FULLMASK, cp[i], off);
    if ((tid & 31) == 0)
#pragma unroll
        for (int i = 0; i < 36; i++) atomicAdd(&rb[i], cp[i]);

    // subset-DP exact assignment (level-synchronous over popcount)
    for (int r = 1; r <= 8; r++) {
        __syncthreads();
        int m = tid;
        if (m >= 1 && m < 256 && __popc(m) == r) {
            float best = 1e30f; int bn = 0;
#pragma unroll
            for (int n = 0; n < 8; n++) {
                if (m & (1 << n)) {
                    float v = dp[m ^ (1 << n)] + csh[(r - 1) * 8 + n];
                    if (v < best) { best = v; bn = n; }
                }
            }
            dp[m] = best; ch[m] = bn;
        }
    }
    __syncthreads();

    if (tid == 0) {
        float nrm[8]; int di = 0;
        for (int k = 0; k < 8; k++) { nrm[k] = fmaxf(sqrtf(rb[di]), 1e-12f); di += 8 - k; }
        float ortho = 0.f, contr = 0.f; int idx = 0;
        for (int k = 0; k < 8; k++)
            for (int j = k; j < 8; j++) {
                float s = rb[idx] / (nrm[k] * nrm[j]);
                if (j == k) { float d = s - 1.f; ortho += d * d; }
                else { ortho += 2.f * s * s; contr += 2.f * fmaxf(s + 0.5f, 0.f); }
                idx++;
            }

        int mask = 255, col[8];
        for (int r = 7; r >= 0; --r) { int n = ch[mask]; col[r] = n; mask ^= (1 << n); }
        float asn = 0.f;
        for (int k = 0; k < 8; k++)
            asn += 0.75f * (red[136 + k] - 0.8f * red[64 + k * 8 + col[k]]);

        float contrib = asn * (1.f / 8388608.f)          // assign mean (B*T*K)
                      + rb[36] * (1.f / 256.f)           // exist mean
                      + 0.1f * ortho * (1.f / 2048.f)    // ortho mean
                      + 0.1f * contr * (1.f / 1792.f)    // contrast
                      + 0.5f * red[144] * (1.f / 1048576.f); // overlap mean
        atomicAdd(&gTotal, contrib);
        __threadfence();
        unsigned old = atomicAdd(&gCount, 1u);
        if (old == 31u) { sLast = 1; sTot = atomicAdd(&gTotal, 0.f); }
    }
    __syncthreads();
    if (sLast) {
        float t = sTot;
        for (int i = tid; i < out_size; i += blockDim.x) out[i] = t;
    }
}

extern "C" void kernel_launch(void* const* d_in, const int* in_sizes, int n_in,
                              void* d_out, int out_size) {
    const float* logits    = (const float*)d_in[0];
    const float* existence = (const float*)d_in[1];
    const float* attract   = (const float*)d_in[2];
    const float* labels    = (const float*)d_in[3];
    const float* olg       = (const float*)d_in[4];
    const float* otg       = (const float*)d_in[5];
    float* out = (float*)d_out;

    dim3 grid(CHUNKS, 32);
    main_kernel<<<grid, 256>>>(logits, labels, olg, otg);
    batch_kernel<<<32, 256>>>(attract, existence, out, out_size);
}

// round 15
// speedup vs baseline: 1.1485x; 1.1358x over previous
#include <cuda_runtime.h>
#include <cuda_bf16.h>
#include <cstddef>

// B=32, T=32768, K=N=8, D=256
// Round-3 champion; single change: CHUNKS 16 -> 32 so grid (32,32)=1024 blocks
// keeps every SM at its full 4-CTA residency (old 512-block grid stranded
// 80/148 SMs at 3 CTAs for the whole kernel).
//   nlp = softplus(-x); p2 = sigmoid(x)^2
//   u = 4*nlp - x ; w = p2*x
//   A[k][n] = sum u*y ; W[k][n] = sum w*y   (mma.m16n8k16 bf16, u/w rows stacked)
//   S1[k] = sum (nlp+x) ; S2[k] = sum p2*(nlp+0.9x)
//   cost = (S1+A)/T ; assign_k = 0.75*(S2[k] - 0.8*W[k][col_k])

#define FULLMASK 0xffffffffu
#define CHUNKS 32
#define TPB_T 1024
#define SLOT 145   // 64 A + 64 W + 8 S1 + 8 S2 + 1 overlap

__device__ float gPart[32 * CHUNKS * SLOT];
__device__ float gTotal;
__device__ unsigned gCount;

__device__ __forceinline__ unsigned pk(float hi, float lo) {
    unsigned r;
    asm("cvt.rn.bf16x2.f32 %0, %1, %2;" : "=r"(r) : "f"(hi), "f"(lo));
    return r;
}

__device__ __forceinline__ void procE(float x, float& u, float& w,
                                      float& s1, float& s2) {
    float e = __expf(-x);
    float tt = 1.f + e;
    float nlp = __logf(tt);
    float r;
    asm("rcp.approx.ftz.f32 %0, %1;" : "=f"(r) : "f"(tt));
    float p2 = r * r;                     // sigmoid(x)^2
    u = fmaf(4.f, nlp, -x);
    w = p2 * x;
    s1 += nlp + x;
    s2 = fmaf(p2, fmaf(0.9f, x, nlp), s2);
}

__global__ void __launch_bounds__(256, 4)
main_kernel(const float* __restrict__ logits, const float* __restrict__ labels,
            const float* __restrict__ olg, const float* __restrict__ otg) {
    __shared__ float sAcc[SLOT];
    const int tid = threadIdx.x;
    if (tid < SLOT) sAcc[tid] = 0.f;
    if (blockIdx.x == 0 && blockIdx.y == 0 && tid == 0) { gTotal = 0.f; gCount = 0u; }
    __syncthreads();

    const int b = blockIdx.y, c = blockIdx.x;
    const int t0 = c * TPB_T;
    const float* lg = logits + (size_t)b * 32768 * 8;
    const float* yb = labels + (size_t)b * 32768 * 8;

    // ---- overlap MSE (coalesced float4) ----
    const float* ob = olg + (size_t)b * 32768 + t0;
    const float* tb = otg + (size_t)b * 32768 + t0;
    float ov = 0.f;
    {
        float4 o4 = reinterpret_cast<const float4*>(ob)[tid];
        float4 t4 = reinterpret_cast<const float4*>(tb)[tid];
        float d0 = o4.x - t4.x, d1 = o4.y - t4.y;
        float d2 = o4.z - t4.z, d3 = o4.w - t4.w;
        ov = fmaf(d0, d0, fmaf(d1, d1, fmaf(d2, d2, d3 * d3)));
    }

    // ---- main mma loop: warp covers 128 t's as 8 steps of 16 ----
    const int wrp = tid >> 5, l = tid & 31;
    const int gid = l >> 2, tg = l & 3;
    const int tw = t0 + wrp * 128;
    const float* xp = lg + (size_t)tw * 8 + gid;
    const float* yp = yb + (size_t)tw * 8 + gid;
    const int o0 = 16 * tg, o1 = o0 + 8, o2 = o0 + 64, o3 = o0 + 72;

    float c0 = 0.f, c1 = 0.f, c2 = 0.f, c3 = 0.f, s1 = 0.f, s2 = 0.f;

#pragma unroll 4
    for (int i = 0; i < 8; i++) {
        const int base = i * 128;
        float x0 = xp[base + o0], x1 = xp[base + o1];
        float x2 = xp[base + o2], x3 = xp[base + o3];
        float y0 = yp[base + o0], y1 = yp[base + o1];
        float y2 = yp[base + o2], y3 = yp[base + o3];
        float u0, u1, u2, u3, w0, w1, w2, w3;
        procE(x0, u0, w0, s1, s2);
        procE(x1, u1, w1, s1, s2);
        procE(x2, u2, w2, s1, s2);
        procE(x3, u3, w3, s1, s2);
        unsigned a0 = pk(u1, u0), a1 = pk(w1, w0);
        unsigned a2 = pk(u3, u2), a3 = pk(w3, w2);
        unsigned b0 = pk(y1, y0), b1 = pk(y3, y2);
        asm("mma.sync.aligned.m16n8k16.row.col.f32.bf16.bf16.f32 "
            "{%0,%1,%2,%3}, {%4,%5,%6,%7}, {%8,%9}, {%0,%1,%2,%3};"
            : "+f"(c0), "+f"(c1), "+f"(c2), "+f"(c3)
            : "r"(a0), "r"(a1), "r"(a2), "r"(a3), "r"(b0), "r"(b1));
    }

    // s1/s2: reduce across the 4 lanes of each gid group
    s1 += __shfl_xor_sync(FULLMASK, s1, 1);
    s1 += __shfl_xor_sync(FULLMASK, s1, 2);
    s2 += __shfl_xor_sync(FULLMASK, s2, 1);
    s2 += __shfl_xor_sync(FULLMASK, s2, 2);
#pragma unroll
    for (int off = 16; off >= 1; off >>= 1) ov += __shfl_down_sync(FULLMASK, ov, off);

    // C frag: c0=(gid,2tg) c1=(gid,2tg+1) rows 0-7 = A ; c2,c3 rows 8-15 = W
    atomicAdd(&sAcc[gid * 8 + 2 * tg],          c0);
    atomicAdd(&sAcc[gid * 8 + 2 * tg + 1],      c1);
    atomicAdd(&sAcc[64 + gid * 8 + 2 * tg],     c2);
    atomicAdd(&sAcc[64 + gid * 8 + 2 * tg + 1], c3);
    if (tg == 0) {
        atomicAdd(&sAcc[128 + gid], s1);
        atomicAdd(&sAcc[136 + gid], s2);
    }
    if (l == 0) atomicAdd(&sAcc[144], ov);
    __syncthreads();

    if (tid < SLOT) gPart[(b * CHUNKS + c) * SLOT + tid] = sAcc[tid];
}

// Per-batch: chunk reduce + gram + subset-DP assignment + existence; last block
// folds everything into the scalar output. (Round-3 validated.)
__global__ void __launch_bounds__(256)
batch_kernel(const float* __restrict__ att, const float* __restrict__ exist,
             float* __restrict__ out, int out_size) {
    __shared__ float red[SLOT];
    __shared__ float rb[37];     // 36 gram upper-tri + [36] existence sum
    __shared__ float csh[64];
    __shared__ float dp[256];
    __shared__ int   ch[256];
    __shared__ int   sLast;
    __shared__ float sTot;
    const int b = blockIdx.x, tid = threadIdx.x;

    if (tid < SLOT) {
        float s = 0.f;
#pragma unroll
        for (int c = 0; c < CHUNKS; c++) s += gPart[(b * CHUNKS + c) * SLOT + tid];
        red[tid] = s;
    }
    if (tid < 37) rb[tid] = 0.f;
    if (tid == 0) { dp[0] = 0.f; sLast = 0; }
    __syncthreads();

    if (tid < 64) {
        int k = tid >> 3;
        float cc = (red[128 + k] + red[tid]) * (1.f / 32768.f);
        if (!(fabsf(cc) <= 1e30f)) cc = 100.f;
        csh[tid] = cc;
    }
    if (tid < 8) {
        float e  = exist[b * 8 + tid];
        float ll = __logf(1.f + __expf(-fabsf(e)));
        float spn = ll + fmaxf(-e, 0.f);
        float spp = ll + fmaxf(e, 0.f);
        atomicAdd(&rb[36], 4.5f * spn + 0.1f * spp);
    }

    // attractor gram: thread = dim d (256 dims, fully parallel)
    const float* ab = att + (size_t)b * 8 * 256;
    float a[8];
#pragma unroll
    for (int k = 0; k < 8; k++) a[k] = ab[k * 256 + tid];
    float cp[36];
    {
        int idx = 0;
#pragma unroll
        for (int k = 0; k < 8; k++)
#pragma unroll
            for (int j = k; j < 8; j++) cp[idx++] = a[k] * a[j];
    }
#pragma unroll
    for (int off = 16; off >= 1; off >>= 1)
#pragma unroll
        for (int i = 0; i < 36; i++) cp[i] += __shfl_down_sync(FULLMASK, cp[i], off);
    if ((tid & 31) == 0)
#pragma unroll
        for (int i = 0; i < 36; i++) atomicAdd(&rb[i], cp[i]);

    // subset-DP exact assignment (level-synchronous over popcount)
    for (int r = 1; r <= 8; r++) {
        __syncthreads();
        int m = tid;
        if (m >= 1 && m < 256 && __popc(m) == r) {
            float best = 1e30f; int bn = 0;
#pragma unroll
            for (int n = 0; n < 8; n++) {
                if (m & (1 << n)) {
                    float v = dp[m ^ (1 << n)] + csh[(r - 1) * 8 + n];
                    if (v < best) { best = v; bn = n; }
                }
            }
            dp[m] = best; ch[m] = bn;
        }
    }
    __syncthreads();

    if (tid == 0) {
        float nrm[8]; int di = 0;
        for (int k = 0; k < 8; k++) { nrm[k] = fmaxf(sqrtf(rb[di]), 1e-12f); di += 8 - k; }
        float ortho = 0.f, contr = 0.f; int idx = 0;
        for (int k = 0; k < 8; k++)
            for (int j = k; j < 8; j++) {
                float s = rb[idx] / (nrm[k] * nrm[j]);
                if (j == k) { float d = s - 1.f; ortho += d * d; }
                else { ortho += 2.f * s * s; contr += 2.f * fmaxf(s + 0.5f, 0.f); }
                idx++;
            }

        int mask = 255, col[8];
        for (int r = 7; r >= 0; --r) { int n = ch[mask]; col[r] = n; mask ^= (1 << n); }
        float asn = 0.f;
        for (int k = 0; k < 8; k++)
            asn += 0.75f * (red[136 + k] - 0.8f * red[64 + k * 8 + col[k]]);

        float contrib = asn * (1.f / 8388608.f)          // assign mean (B*T*K)
                      + rb[36] * (1.f / 256.f)           // exist mean
                      + 0.1f * ortho * (1.f / 2048.f)    // ortho mean
                      + 0.1f * contr * (1.f / 1792.f)    // contrast
                      + 0.5f * red[144] * (1.f / 1048576.f); // overlap mean
        atomicAdd(&gTotal, contrib);
        __threadfence();
        unsigned old = atomicAdd(&gCount, 1u);
        if (old == 31u) { sLast = 1; sTot = atomicAdd(&gTotal, 0.f); }
    }
    __syncthreads();
    if (sLast) {
        float t = sTot;
        for (int i = tid; i < out_size; i += blockDim.x) out[i] = t;
    }
}

extern "C" void kernel_launch(void* const* d_in, const int* in_sizes, int n_in,
                              void* d_out, int out_size) {
    const float* logits    = (const float*)d_in[0];
    const float* existence = (const float*)d_in[1];
    const float* attract   = (const float*)d_in[2];
    const float* labels    = (const float*)d_in[3];
    const float* olg       = (const float*)d_in[4];
    const float* otg       = (const float*)d_in[5];
    float* out = (float*)d_out;

    dim3 grid(CHUNKS, 32);
    main_kernel<<<grid, 256>>>(logits, labels, olg, otg);
    batch_kernel<<<32, 256>>>(attract, existence, out, out_size);
}